// round 2
// baseline (speedup 1.0000x reference)
#include <cuda_runtime.h>
#include <math.h>

#define BB    8
#define RR    128
#define FM    19
#define FM2   (FM*FM)      // 361
#define PS    7
#define NPOS  49
#define C0    1024
#define C1    256
#define C2    256
#define C3    32
#define NSLOT (BB*RR)      // 1024
#define SMAXC 18

// output layout: er_c [B,1,R,4] | out_c [B,R,32,7,7] | keep_count [B]
#define OUT_ER   0
#define OUT_FEAT (NSLOT*4)                       // 4096
#define OUT_KEEP (OUT_FEAT + NSLOT*C3*NPOS)      // 4096 + 1605632

// ---------------- static device scratch (no allocs allowed) ----------------
__device__ int   g_keep[BB];
__device__ int   g_ybase[NSLOT*PS], g_ylen[NSLOT*PS];
__device__ int   g_xbase[NSLOT*PS], g_xlen[NSLOT*PS];
__device__ float g_ft[BB*FM2*C0];            // [b][y*19+x][c]   11.8 MB
__device__ float g_pooled[NSLOT*NPOS*C0];    // [slot][pos][c]   205 MB
__device__ float g_x1[NSLOT*NPOS*C1];        // [slot][pos][oc]   51 MB
__device__ float g_x2[NSLOT*NPOS*C2];        //                   51 MB
__device__ float g_W1t[C0*9*C1];             // [ic][k][oc]
__device__ float g_W2t[C1*9*C2];
__device__ float g_W3t[C2*C3];               // [ic][oc]

// ---------------- ROI decode + per-batch stable compaction -----------------
__global__ void k_setup(const float* __restrict__ roi, float* __restrict__ out) {
    int b = blockIdx.x, r = threadIdx.x;
    const float* p = roi + (size_t)(b*RR + r)*5;
    int rl[4], cc[4];
#pragma unroll
    for (int k = 0; k < 4; ++k) {
        float v = p[1+k] * 18.75f;         // * IMG/16 in fp32, exact as reference
        rl[k] = (int)v;                    // trunc toward zero == astype(int32)
        int c = rl[k] < 0 ? 0 : rl[k];
        cc[k] = c > SMAXC ? SMAXC : c;
    }
    int valid = (cc[2] > cc[0]) && (cc[3] > cc[1]);

    __shared__ int flags[RR];
    __shared__ int pre[RR];
    flags[r] = valid;
    __syncthreads();
    if (r == 0) {
        int run = 0;
        for (int i = 0; i < RR; ++i) { pre[i] = run; run += flags[i]; }
        g_keep[b] = run;
        out[OUT_KEEP + b] = (float)run;
    }
    __syncthreads();

    if (valid) {
        int slot = b*RR + pre[r];
#pragma unroll
        for (int k = 0; k < 4; ++k)
            out[OUT_ER + slot*4 + k] = (float)rl[k] * (16.0f/300.0f);
        int xmin = cc[0], ymin = cc[1], xmax = cc[2], ymax = cc[3];
        int Hy = ymax - ymin + 1, Hx = xmax - xmin + 1;
#pragma unroll
        for (int i = 0; i < PS; ++i) {
            int sy = (i*Hy)/PS,  ey = ((i+1)*Hy + PS - 1)/PS;
            g_ybase[slot*PS+i] = ymin + sy;  g_ylen[slot*PS+i] = ey - sy;
            int sx = (i*Hx)/PS,  ex = ((i+1)*Hx + PS - 1)/PS;
            g_xbase[slot*PS+i] = xmin + sx;  g_xlen[slot*PS+i] = ex - sx;
        }
    }
}

// ---------------- features [b][c][y][x] -> [b][yx][c] (tiled) ---------------
__global__ void k_ftrans(const float* __restrict__ f) {
    __shared__ float t[32][33];
    int b  = blockIdx.z;
    int yx0 = blockIdx.x*32, c0 = blockIdx.y*32;
    int tx = threadIdx.x, ty = threadIdx.y;
    int yx = yx0 + tx, c = c0 + ty;
    if (yx < FM2) t[ty][tx] = f[((size_t)b*C0 + c)*FM2 + yx];
    __syncthreads();
    int c2 = c0 + tx, yx2 = yx0 + ty;
    if (yx2 < FM2) g_ft[((size_t)b*FM2 + yx2)*C0 + c2] = t[tx][ty];
}

// ---------------- weight transposes: [oc][ic][3][3] -> [ic][k][oc] ----------
__global__ void k_w1t(const float* __restrict__ w) {
    int ick = blockIdx.x, oc = threadIdx.x;
    int ic = ick/9, k = ick - ic*9;
    g_W1t[(size_t)ick*C1 + oc] = w[((size_t)oc*C0 + ic)*9 + k];
}
__global__ void k_w2t(const float* __restrict__ w) {
    int ick = blockIdx.x, oc = threadIdx.x;
    int ic = ick/9, k = ick - ic*9;
    g_W2t[(size_t)ick*C2 + oc] = w[((size_t)oc*C1 + ic)*9 + k];
}
__global__ void k_w3t(const float* __restrict__ w) {
    int oc = blockIdx.x, ic = threadIdx.x;    // <<<32,256>>>
    g_W3t[ic*C3 + oc] = w[oc*C2 + ic];
}

// ---------------- adaptive pooling on valid slots only ----------------------
__global__ void k_pool() {
    int b = blockIdx.z, j = blockIdx.y;
    if (j >= g_keep[b]) return;
    int slot = b*RR + j;
    int c = blockIdx.x*128 + threadIdx.x;

    __shared__ int yb[PS], yl[PS], xb[PS], xl[PS];
    if (threadIdx.x < PS) {
        int i = threadIdx.x;
        yb[i] = g_ybase[slot*PS+i]; yl[i] = g_ylen[slot*PS+i];
        xb[i] = g_xbase[slot*PS+i]; xl[i] = g_xlen[slot*PS+i];
    }
    __syncthreads();

    const float* fb = g_ft + (size_t)b*FM2*C0 + c;
    float* op = g_pooled + (size_t)slot*NPOS*C0 + c;
#pragma unroll
    for (int p = 0; p < PS; ++p) {
        int y0 = yb[p], ny = yl[p];
        float ry = 1.0f/(float)ny;
#pragma unroll
        for (int q = 0; q < PS; ++q) {
            int x0 = xb[q], nx = xl[q];
            float s = 0.f;
            for (int dy = 0; dy < ny; ++dy) {
                const float* row = fb + ((size_t)((y0+dy)*FM + x0))*C0;
                for (int dx = 0; dx < nx; ++dx) s += row[(size_t)dx*C0];
            }
            op[(size_t)(p*PS + q)*C0] = s * ry * (1.0f/(float)nx);
        }
    }
}

// ---------------- 3x3 conv + BN + ReLU, CTA=slot, thread=oc -----------------
// STAGE 1: g_pooled(IC=1024) -> g_x1 ; STAGE 2: g_x1(IC=256) -> g_x2
template<int STAGE>
__global__ void __launch_bounds__(256, 2) k_conv3x3(
    const float* __restrict__ bias, const float* __restrict__ gg,
    const float* __restrict__ be,   const float* __restrict__ mm,
    const float* __restrict__ vv)
{
    constexpr int IC = (STAGE == 1) ? C0 : C1;
    int b = blockIdx.x >> 7, j = blockIdx.x & 127;
    if (j >= g_keep[b]) return;
    int slot = blockIdx.x;

    const float* in  = (STAGE == 1) ? (const float*)g_pooled : (const float*)g_x1;
    const float* wt  = (STAGE == 1) ? (const float*)g_W1t    : (const float*)g_W2t;
    float*       outb= (STAGE == 1) ? (float*)g_x1           : (float*)g_x2;

    __shared__ __align__(16) float sin[64*108];   // [ic][9 rows][12 cols] zero-padded
    for (int i = threadIdx.x; i < 64*108; i += 256) sin[i] = 0.f;
    __syncthreads();

    int oc = threadIdx.x;
    float acc[NPOS];
#pragma unroll
    for (int i = 0; i < NPOS; ++i) acc[i] = 0.f;

    const float* inp = in + (size_t)slot*NPOS*IC;

#pragma unroll 1
    for (int ch = 0; ch < IC/64; ++ch) {
        // stage input chunk into padded smem (coalesced over ic)
        for (int idx = threadIdx.x; idx < 64*NPOS; idx += 256) {
            int icl = idx & 63, pos = idx >> 6;
            int py = pos/7, px = pos - py*7;
            sin[icl*108 + (py+1)*12 + (px+1)] = inp[(size_t)pos*IC + ch*64 + icl];
        }
        __syncthreads();

        const float* wp = wt + ((size_t)(ch*64)*9)*256 + oc;
        float w[9];
#pragma unroll
        for (int k = 0; k < 9; ++k) w[k] = wp[k*256];

#pragma unroll 1
        for (int ic = 0; ic < 64; ++ic) {
            // prefetch next ic's weights (hides L2 latency behind the 441 FMAs)
            float wn[9];
            {
                int icn = (ic + 1 < 64) ? ic + 1 : 63;
                const float* wq = wt + ((size_t)(ch*64 + icn)*9)*256 + oc;
#pragma unroll
                for (int k = 0; k < 9; ++k) wn[k] = wq[k*256];
            }
            const float4* rp = (const float4*)(sin + ic*108);
#pragma unroll
            for (int R = 0; R < 9; ++R) {   // smem row R == input row R-1
                float4 f0 = rp[R*3+0], f1 = rp[R*3+1], f2 = rp[R*3+2];
                float r[12] = {f0.x,f0.y,f0.z,f0.w, f1.x,f1.y,f1.z,f1.w,
                               f2.x,f2.y,f2.z,f2.w};
                int prlo = (R-2 < 0) ? 0 : R-2;
                int prhi = (R > 6) ? 6 : R;
#pragma unroll
                for (int pr = prlo; pr <= prhi; ++pr) {
                    int ky = R - pr;
#pragma unroll
                    for (int px = 0; px < 7; ++px) {
                        float a = acc[pr*7 + px];
                        a = fmaf(w[ky*3+0], r[px+0], a);
                        a = fmaf(w[ky*3+1], r[px+1], a);
                        a = fmaf(w[ky*3+2], r[px+2], a);
                        acc[pr*7 + px] = a;
                    }
                }
            }
#pragma unroll
            for (int k = 0; k < 9; ++k) w[k] = wn[k];
        }
        __syncthreads();
    }

    // fused bias + BN + ReLU epilogue
    float sc = gg[oc] * rsqrtf(vv[oc] + 1e-5f);
    float sh = bias[oc]*sc + be[oc] - mm[oc]*sc;
    float* op = outb + (size_t)slot*NPOS*256 + oc;
#pragma unroll
    for (int p = 0; p < NPOS; ++p) {
        float val = fmaf(acc[p], sc, sh);
        op[(size_t)p*256] = val > 0.f ? val : 0.f;
    }
}

// ---------------- 1x1 conv + BN + ReLU -> final output ----------------------
__global__ void k_conv1x1(const float* __restrict__ gg, const float* __restrict__ be,
                          const float* __restrict__ mm, const float* __restrict__ vv,
                          float* __restrict__ out)
{
    int b = blockIdx.x >> 7, j = blockIdx.x & 127;
    if (j >= g_keep[b]) return;
    int slot = blockIdx.x;

    __shared__ float sw[C2*C3];
    for (int i = threadIdx.x; i < C2*C3; i += 256) sw[i] = g_W3t[i];
    __syncthreads();

    const float* xp = g_x2 + (size_t)slot*NPOS*C2;
    for (int idx = threadIdx.x; idx < NPOS*C3; idx += 256) {
        int oc = idx & 31, pos = idx >> 5;     // whole warp shares pos -> broadcast loads
        const float* xr = xp + (size_t)pos*C2;
        float acc = 0.f;
#pragma unroll 8
        for (int ic = 0; ic < C2; ++ic) acc = fmaf(xr[ic], sw[ic*C3 + oc], acc);
        float sc = gg[oc] * rsqrtf(vv[oc] + 1e-5f);
        float sh = be[oc] - mm[oc]*sc;         // conv3 has no bias
        float val = fmaf(acc, sc, sh);
        out[OUT_FEAT + ((size_t)slot*C3 + oc)*NPOS + pos] = val > 0.f ? val : 0.f;
    }
}

// ---------------------------------------------------------------------------
extern "C" void kernel_launch(void* const* d_in, const int* in_sizes, int n_in,
                              void* d_out, int out_size) {
    const float* roi  = (const float*)d_in[0];
    const float* feat = (const float*)d_in[1];
    const float* W1   = (const float*)d_in[2];
    const float* b1   = (const float*)d_in[3];
    const float* g1   = (const float*)d_in[4];
    const float* be1  = (const float*)d_in[5];
    const float* m1   = (const float*)d_in[6];
    const float* v1   = (const float*)d_in[7];
    const float* W2   = (const float*)d_in[8];
    const float* b2   = (const float*)d_in[9];
    const float* g2   = (const float*)d_in[10];
    const float* be2  = (const float*)d_in[11];
    const float* m2   = (const float*)d_in[12];
    const float* v2   = (const float*)d_in[13];
    const float* W3   = (const float*)d_in[14];
    const float* g3   = (const float*)d_in[15];
    const float* be3  = (const float*)d_in[16];
    const float* m3   = (const float*)d_in[17];
    const float* v3   = (const float*)d_in[18];
    float* out = (float*)d_out;

    // invalid ROI slots (er, out_c tail) must be exactly zero
    cudaMemsetAsync(d_out, 0, (size_t)out_size * sizeof(float));

    k_setup<<<BB, RR>>>(roi, out);
    k_ftrans<<<dim3(12, 32, BB), dim3(32, 32)>>>(feat);
    k_w1t<<<C0*9, C1>>>(W1);
    k_w2t<<<C1*9, C2>>>(W2);
    k_w3t<<<C3, C2>>>(W3);

    k_pool<<<dim3(8, RR, BB), 128>>>();
    k_conv3x3<1><<<NSLOT, 256>>>(b1, g1, be1, m1, v1);
    k_conv3x3<2><<<NSLOT, 256>>>(b2, g2, be2, m2, v2);
    k_conv1x1<<<NSLOT, 256>>>(g3, be3, m3, v3, out);
}

// round 4
// speedup vs baseline: 1.6104x; 1.6104x over previous
#include <cuda_runtime.h>
#include <cuda_bf16.h>
#include <math.h>
#include <stdint.h>

#define BB    8
#define RR    128
#define FM    19
#define FM2   (FM*FM)
#define PS    7
#define NPOS  49
#define C0    1024
#define C1    256
#define C2    256
#define C3    32
#define NSLOT (BB*RR)
#define SMAXC 18

#define OUT_ER   0
#define OUT_FEAT (NSLOT*4)
#define OUT_KEEP (OUT_FEAT + NSLOT*C3*NPOS)

// GEMM tiling
#define KC    32
#define NCH1  (9*C0/KC)     // 288
#define NCH2  (9*C1/KC)     // 72
#define A_T   (128*80)      // 10240 B per A term tile (stride-80 rows)
#define B_T   (256*80)      // 20480 B per B term tile
#define BUF   (2*A_T + 2*B_T)   // 61440
#define DSMEM (2*BUF)           // 122880

// ---------------- static device scratch ------------------------------------
__device__ int   g_keep[BB];
__device__ int   g_npairs;
__device__ int2  g_pairs[512];
__device__ int   g_ybase[NSLOT*PS], g_ylen[NSLOT*PS];
__device__ int   g_xbase[NSLOT*PS], g_xlen[NSLOT*PS];
__device__ float g_ft[BB*FM2*C0];
__device__ __nv_bfloat16 g_pph[(size_t)NSLOT*NPOS*C0];
__device__ __nv_bfloat16 g_ppl[(size_t)NSLOT*NPOS*C0];
__device__ __nv_bfloat16 g_x1h[(size_t)NSLOT*NPOS*C1];
__device__ __nv_bfloat16 g_x1l[(size_t)NSLOT*NPOS*C1];
__device__ float g_x2[(size_t)NSLOT*NPOS*C2];
__device__ __nv_bfloat16 g_W1b[2u*NCH1*256*KC];   // [term][kc][oc][32]
__device__ __nv_bfloat16 g_W2b[2u*NCH2*256*KC];
__device__ float g_W3t[C2*C3];

// ---------------- PTX helpers (non-'a' ISA only) ----------------------------
__device__ __forceinline__ uint32_t smem_u32(const void* p) {
    uint32_t a;
    asm("{ .reg .u64 t; cvta.to.shared.u64 t, %1; cvt.u32.u64 %0, t; }" : "=r"(a) : "l"(p));
    return a;
}
__device__ __forceinline__ void cpa16(uint32_t dst, const void* src, int ok) {
    int sz = ok ? 16 : 0;
    asm volatile("cp.async.cg.shared.global [%0], [%1], 16, %2;"
                 :: "r"(dst), "l"(src), "r"(sz) : "memory");
}
__device__ __forceinline__ void cpa_commit() {
    asm volatile("cp.async.commit_group;" ::: "memory");
}
__device__ __forceinline__ void ldsm4(uint32_t* r, uint32_t a) {
    asm volatile("ldmatrix.sync.aligned.m8n8.x4.shared.b16 {%0,%1,%2,%3}, [%4];"
                 : "=r"(r[0]), "=r"(r[1]), "=r"(r[2]), "=r"(r[3]) : "r"(a));
}
__device__ __forceinline__ void mma_bf16(float* c, const uint32_t* a, const uint32_t* b) {
    asm volatile("mma.sync.aligned.m16n8k16.row.col.f32.bf16.bf16.f32 "
                 "{%0,%1,%2,%3}, {%4,%5,%6,%7}, {%8,%9}, {%0,%1,%2,%3};"
                 : "+f"(c[0]), "+f"(c[1]), "+f"(c[2]), "+f"(c[3])
                 : "r"(a[0]), "r"(a[1]), "r"(a[2]), "r"(a[3]), "r"(b[0]), "r"(b[1]));
}

// ---------------- ROI decode + per-batch stable compaction -----------------
__global__ void k_setup(const float* __restrict__ roi, float* __restrict__ out) {
    int b = blockIdx.x, r = threadIdx.x;
    const float* p = roi + (size_t)(b*RR + r)*5;
    int rl[4], cc[4];
#pragma unroll
    for (int k = 0; k < 4; ++k) {
        float v = p[1+k] * 18.75f;
        rl[k] = (int)v;
        int c = rl[k] < 0 ? 0 : rl[k];
        cc[k] = c > SMAXC ? SMAXC : c;
    }
    int valid = (cc[2] > cc[0]) && (cc[3] > cc[1]);

    __shared__ int flags[RR], pre[RR];
    flags[r] = valid;
    __syncthreads();
    if (r == 0) {
        int run = 0;
        for (int i = 0; i < RR; ++i) { pre[i] = run; run += flags[i]; }
        g_keep[b] = run;
        out[OUT_KEEP + b] = (float)run;
    }
    __syncthreads();

    if (valid) {
        int slot = b*RR + pre[r];
#pragma unroll
        for (int k = 0; k < 4; ++k)
            out[OUT_ER + slot*4 + k] = (float)rl[k] * (16.0f/300.0f);
        int xmin = cc[0], ymin = cc[1], xmax = cc[2], ymax = cc[3];
        int Hy = ymax - ymin + 1, Hx = xmax - xmin + 1;
#pragma unroll
        for (int i = 0; i < PS; ++i) {
            int sy = (i*Hy)/PS,  ey = ((i+1)*Hy + PS - 1)/PS;
            g_ybase[slot*PS+i] = ymin + sy;  g_ylen[slot*PS+i] = ey - sy;
            int sx = (i*Hx)/PS,  ex = ((i+1)*Hx + PS - 1)/PS;
            g_xbase[slot*PS+i] = xmin + sx;  g_xlen[slot*PS+i] = ex - sx;
        }
    }
}

__global__ void k_pairs() {
    if (threadIdx.x == 0) {
        int n = 0;
        for (int b = 0; b < BB; ++b) {
            int np = (g_keep[b] + 1) >> 1;
            for (int j = 0; j < np; ++j) g_pairs[n++] = make_int2(b, j);
        }
        g_npairs = n;
    }
}

// ---------------- features [b][c][y][x] -> [b][yx][c] -----------------------
__global__ void k_ftrans(const float* __restrict__ f) {
    __shared__ float t[32][33];
    int b  = blockIdx.z;
    int yx0 = blockIdx.x*32, c0 = blockIdx.y*32;
    int tx = threadIdx.x, ty = threadIdx.y;
    int yx = yx0 + tx, c = c0 + ty;
    if (yx < FM2) t[ty][tx] = f[((size_t)b*C0 + c)*FM2 + yx];
    __syncthreads();
    int c2 = c0 + tx, yx2 = yx0 + ty;
    if (yx2 < FM2) g_ft[((size_t)b*FM2 + yx2)*C0 + c2] = t[tx][ty];
}

// ---------------- weight split: [oc][ic][3][3] -> [term][kc][oc][32] bf16 ---
template<int IC>
__global__ void k_wsplit(const float* __restrict__ W) {
    constexpr int ICB = IC/KC;
    constexpr int NC  = 9*ICB;
    __nv_bfloat16* Wb = (IC == 1024) ? g_W1b : g_W2b;
    int e = blockIdx.x*256 + threadIdx.x;
    int term = e / (NC*256*KC);
    int rem  = e % (NC*256*KC);
    int kc = rem >> 13, r2 = rem & 8191, oc = r2 >> 5, t = r2 & 31;
    int tap = kc / ICB, icb = kc % ICB;
    int ic = icb*KC + t;
    float w = W[((size_t)oc*IC + ic)*9 + tap];
    __nv_bfloat16 h = __float2bfloat16(w);
    float val = term ? (w - __bfloat162float(h)) : w;
    Wb[e] = __float2bfloat16(val);
}

__global__ void k_w3t(const float* __restrict__ w) {
    int oc = blockIdx.x, ic = threadIdx.x;
    g_W3t[ic*C3 + oc] = w[oc*C2 + ic];
}

// ---------------- adaptive pooling -> bf16 hi/lo -----------------------------
__global__ void k_pool() {
    int b = blockIdx.z, j = blockIdx.y;
    if (j >= g_keep[b]) return;
    int slot = b*RR + j;
    int c = blockIdx.x*128 + threadIdx.x;

    __shared__ int yb[PS], yl[PS], xb[PS], xl[PS];
    if (threadIdx.x < PS) {
        int i = threadIdx.x;
        yb[i] = g_ybase[slot*PS+i]; yl[i] = g_ylen[slot*PS+i];
        xb[i] = g_xbase[slot*PS+i]; xl[i] = g_xlen[slot*PS+i];
    }
    __syncthreads();

    const float* fb = g_ft + (size_t)b*FM2*C0 + c;
#pragma unroll
    for (int p = 0; p < PS; ++p) {
        int y0 = yb[p], ny = yl[p];
        float ry = 1.0f/(float)ny;
#pragma unroll
        for (int q = 0; q < PS; ++q) {
            int x0 = xb[q], nx = xl[q];
            float s = 0.f;
            for (int dy = 0; dy < ny; ++dy) {
                const float* row = fb + ((size_t)((y0+dy)*FM + x0))*C0;
                for (int dx = 0; dx < nx; ++dx) s += row[(size_t)dx*C0];
            }
            s = s * ry * (1.0f/(float)nx);
            size_t idx = ((size_t)slot*NPOS + p*PS + q)*C0 + c;
            __nv_bfloat16 h = __float2bfloat16(s);
            g_pph[idx] = h;
            g_ppl[idx] = __float2bfloat16(s - __bfloat162float(h));
        }
    }
}

// ---------------- mma.sync bf16 implicit-GEMM 3x3 conv + BN + ReLU ----------
// CTA: M=128 (pair of ROIs x49 +pad), N=256, 512 thr = 16 warps (2M x 8N),
// warp tile 64x32, K staged in 32-chunks, cp.async double buffer.
template<int STAGE>
__global__ void __launch_bounds__(512, 1) k_mma(
    const float* __restrict__ bias, const float* __restrict__ gg,
    const float* __restrict__ be,   const float* __restrict__ mm,
    const float* __restrict__ vv)
{
    constexpr int IC  = (STAGE == 1) ? C0 : C1;
    constexpr int ICB = IC/KC;
    constexpr int NC  = 9*ICB;

    int bx = blockIdx.x;
    if (bx >= g_npairs) return;
    int2 pr2 = g_pairs[bx];
    int b = pr2.x, j = pr2.y;
    int keep = g_keep[b];
    int slot0 = b*RR + 2*j;
    int tid = threadIdx.x, wid = tid >> 5, lane = tid & 31;
    int wm = wid >> 3, wn = wid & 7;             // warp grid 2 x 8
    int R0 = wm*64, Cw = wn*32;

    const __nv_bfloat16* inH = (STAGE == 1) ? g_pph : g_x1h;
    const __nv_bfloat16* inL = (STAGE == 1) ? g_ppl : g_x1l;
    const __nv_bfloat16* Wb  = (STAGE == 1) ? g_W1b : g_W2b;

    extern __shared__ __align__(16) char dyn[];
    uint32_t base = smem_u32(dyn);

    __shared__ float s_sc[256], s_sh[256];
    if (tid < 256) {
        float sc = gg[tid] * rsqrtf(vv[tid] + 1e-5f);
        s_sc[tid] = sc;
        s_sh[tid] = bias[tid]*sc + be[tid] - mm[tid]*sc;
    }

    // ---- staging lambda-ish: issue 6 cp.async for chunk c into buffer buf ----
    auto stage = [&](int c, int buf) {
        int tap = c / ICB, icb = c - tap*ICB;
        int ky = tap/3, kx = tap - ky*3;
        // A: 128 rows x 4 units, 1 unit/thread
        int row = tid >> 2, u = tid & 3;
        int r2 = row >= 49 ? 1 : 0;
        int p = row - 49*r2;
        int py = p/7, px = p - py*7;
        int sy = py + ky - 1, sx = px + kx - 1;
        int ok = (row < 98) && ((2*j + r2) < keep) &&
                 sy >= 0 && sy < 7 && sx >= 0 && sx < 7;
        size_t off = ok ? (((size_t)(slot0 + r2)*NPOS + sy*7 + sx)*IC + icb*KC + u*8) : 0;
        uint32_t dA = base + buf*BUF + row*80 + u*16;
        cpa16(dA,       inH + off, ok);
        cpa16(dA + A_T, inL + off, ok);
        // B: 256 rows x 4 units, 2 units/thread
#pragma unroll
        for (int i = 0; i < 2; ++i) {
            int g = tid + i*512;
            int r = g >> 2, uu = g & 3;
            const __nv_bfloat16* s = Wb + ((size_t)c*256 + r)*KC + uu*8;
            uint32_t dB = base + buf*BUF + 2*A_T + r*80 + uu*16;
            cpa16(dB,       s,                         1);
            cpa16(dB + B_T, s + (size_t)NC*256*KC,     1);
        }
    };

    float acc[64];
#pragma unroll
    for (int i = 0; i < 64; ++i) acc[i] = 0.f;

    stage(0, 0); cpa_commit();
    stage(1, 1); cpa_commit();

    int arow = lane & 15, asel = lane >> 4;
    int brow = (lane & 7) + ((lane >> 4) << 3), bsel = (lane >> 3) & 1;

#pragma unroll 1
    for (int c = 0; c < NC; ++c) {
        if (c + 1 < NC) asm volatile("cp.async.wait_group 1;" ::: "memory");
        else            asm volatile("cp.async.wait_group 0;" ::: "memory");
        __syncthreads();

        int buf = c & 1;
        uint32_t Ah = base + buf*BUF;
        uint32_t Al = Ah + A_T;
        uint32_t Bh = Ah + 2*A_T;
        uint32_t Bl = Bh + B_T;

#pragma unroll
        for (int ks = 0; ks < 2; ++ks) {
            uint32_t au = (2*ks + asel)*16;
            uint32_t bu = (2*ks + bsel)*16;
            uint32_t ah[16], al[16], bfr[8];
#pragma unroll
            for (int i = 0; i < 4; ++i)
                ldsm4(ah + 4*i, Ah + (R0 + i*16 + arow)*80 + au);
#pragma unroll
            for (int h = 0; h < 2; ++h)
                ldsm4(bfr + 4*h, Bh + (Cw + h*16 + brow)*80 + bu);
#pragma unroll
            for (int i = 0; i < 4; ++i)
#pragma unroll
                for (int jj = 0; jj < 4; ++jj)
                    mma_bf16(acc + (i*4+jj)*4, ah + 4*i, bfr + (jj>>1)*4 + (jj&1)*2);
#pragma unroll
            for (int i = 0; i < 4; ++i)
                ldsm4(al + 4*i, Al + (R0 + i*16 + arow)*80 + au);
#pragma unroll
            for (int i = 0; i < 4; ++i)
#pragma unroll
                for (int jj = 0; jj < 4; ++jj)
                    mma_bf16(acc + (i*4+jj)*4, al + 4*i, bfr + (jj>>1)*4 + (jj&1)*2);
#pragma unroll
            for (int h = 0; h < 2; ++h)
                ldsm4(bfr + 4*h, Bl + (Cw + h*16 + brow)*80 + bu);
#pragma unroll
            for (int i = 0; i < 4; ++i)
#pragma unroll
                for (int jj = 0; jj < 4; ++jj)
                    mma_bf16(acc + (i*4+jj)*4, ah + 4*i, bfr + (jj>>1)*4 + (jj&1)*2);
        }
        __syncthreads();
        if (c + 2 < NC) { stage(c + 2, buf); cpa_commit(); }
    }

    // ---- epilogue: BN + ReLU, scatter to [slot][pos][oc] ----
#pragma unroll
    for (int i = 0; i < 4; ++i) {
#pragma unroll
        for (int half = 0; half < 2; ++half) {
            int m = R0 + i*16 + (lane >> 2) + half*8;
            int r2 = m >= 49 ? 1 : 0;
            int p = m - 49*r2;
            if (m < 98 && (2*j + r2) < keep) {
                size_t ob = ((size_t)(slot0 + r2)*NPOS + p)*256;
#pragma unroll
                for (int jj = 0; jj < 4; ++jj) {
                    int col = Cw + jj*8 + (lane & 3)*2;
                    float v0 = fmaf(acc[(i*4+jj)*4 + half*2    ], s_sc[col],   s_sh[col]);
                    float v1 = fmaf(acc[(i*4+jj)*4 + half*2 + 1], s_sc[col+1], s_sh[col+1]);
                    v0 = v0 > 0.f ? v0 : 0.f;
                    v1 = v1 > 0.f ? v1 : 0.f;
                    if (STAGE == 1) {
                        __nv_bfloat16 h0 = __float2bfloat16(v0), h1 = __float2bfloat16(v1);
                        float l0 = v0 - __bfloat162float(h0), l1 = v1 - __bfloat162float(h1);
                        unsigned hp = ((unsigned)__bfloat16_as_ushort(h1) << 16) | __bfloat16_as_ushort(h0);
                        unsigned lp = ((unsigned)__bfloat16_as_ushort(__float2bfloat16(l1)) << 16)
                                    | __bfloat16_as_ushort(__float2bfloat16(l0));
                        ((unsigned*)g_x1h)[(ob + col) >> 1] = hp;
                        ((unsigned*)g_x1l)[(ob + col) >> 1] = lp;
                    } else {
                        *(float2*)(g_x2 + ob + col) = make_float2(v0, v1);
                    }
                }
            }
        }
    }
}

// ---------------- 1x1 conv + BN + ReLU -> final output ----------------------
__global__ void k_conv1x1(const float* __restrict__ gg, const float* __restrict__ be,
                          const float* __restrict__ mm, const float* __restrict__ vv,
                          float* __restrict__ out)
{
    int b = blockIdx.x >> 7, j = blockIdx.x & 127;
    if (j >= g_keep[b]) return;
    int slot = blockIdx.x;

    __shared__ float sw[C2*C3];
    for (int i = threadIdx.x; i < C2*C3; i += 256) sw[i] = g_W3t[i];
    __syncthreads();

    const float* xp = g_x2 + (size_t)slot*NPOS*C2;
    for (int idx = threadIdx.x; idx < NPOS*C3; idx += 256) {
        int oc = idx & 31, pos = idx >> 5;
        const float* xr = xp + (size_t)pos*C2;
        float acc = 0.f;
#pragma unroll 8
        for (int ic = 0; ic < C2; ++ic) acc = fmaf(xr[ic], sw[ic*C3 + oc], acc);
        float sc = gg[oc] * rsqrtf(vv[oc] + 1e-5f);
        float sh = be[oc] - mm[oc]*sc;
        float val = fmaf(acc, sc, sh);
        out[OUT_FEAT + ((size_t)slot*C3 + oc)*NPOS + pos] = val > 0.f ? val : 0.f;
    }
}

// ---------------------------------------------------------------------------
extern "C" void kernel_launch(void* const* d_in, const int* in_sizes, int n_in,
                              void* d_out, int out_size) {
    const float* roi  = (const float*)d_in[0];
    const float* feat = (const float*)d_in[1];
    const float* W1   = (const float*)d_in[2];
    const float* b1   = (const float*)d_in[3];
    const float* g1   = (const float*)d_in[4];
    const float* be1  = (const float*)d_in[5];
    const float* m1   = (const float*)d_in[6];
    const float* v1   = (const float*)d_in[7];
    const float* W2   = (const float*)d_in[8];
    const float* b2   = (const float*)d_in[9];
    const float* g2   = (const float*)d_in[10];
    const float* be2  = (const float*)d_in[11];
    const float* m2   = (const float*)d_in[12];
    const float* v2   = (const float*)d_in[13];
    const float* W3   = (const float*)d_in[14];
    const float* g3   = (const float*)d_in[15];
    const float* be3  = (const float*)d_in[16];
    const float* m3   = (const float*)d_in[17];
    const float* v3   = (const float*)d_in[18];
    float* out = (float*)d_out;

    cudaFuncSetAttribute(k_mma<1>, cudaFuncAttributeMaxDynamicSharedMemorySize, DSMEM);
    cudaFuncSetAttribute(k_mma<2>, cudaFuncAttributeMaxDynamicSharedMemorySize, DSMEM);

    cudaMemsetAsync(d_out, 0, (size_t)out_size * sizeof(float));

    k_setup<<<BB, RR>>>(roi, out);
    k_pairs<<<1, 32>>>();
    k_ftrans<<<dim3(12, 32, BB), dim3(32, 32)>>>(feat);
    k_wsplit<C0><<<2*NCH1*256*KC/256, 256>>>(W1);
    k_wsplit<C1><<<2*NCH2*256*KC/256, 256>>>(W2);
    k_w3t<<<C3, C2>>>(W3);

    k_pool<<<dim3(8, RR, BB), 128>>>();
    k_mma<1><<<512, 512, DSMEM>>>(b1, g1, be1, m1, v1);
    k_mma<2><<<512, 512, DSMEM>>>(b2, g2, be2, m2, v2);
    k_conv1x1<<<NSLOT, 256>>>(g3, be3, m3, v3, out);
}

// round 5
// speedup vs baseline: 2.2686x; 1.4087x over previous
#include <cuda_runtime.h>
#include <cuda_fp16.h>
#include <math.h>
#include <stdint.h>

#define BB    8
#define RR    128
#define FM    19
#define FM2   (FM*FM)
#define PS    7
#define NPOS  49
#define C0    1024
#define C1    256
#define C2    256
#define C3    32
#define NSLOT (BB*RR)
#define SMAXC 18

#define OUT_ER   0
#define OUT_FEAT (NSLOT*4)
#define OUT_KEEP (OUT_FEAT + NSLOT*C3*NPOS)

// GEMM tiling: K-chunk 64
#define KC    64
#define NCH1  (9*C0/KC)         // 144
#define NCH2  (9*C1/KC)         // 36
#define STRD  144               // 128B data + 16B pad per row
#define A_T   (128*STRD)        // 18432
#define B_T   (256*STRD)        // 36864
#define BUF   (A_T + 2*B_T)     // 92160
#define DSMEM (2*BUF)           // 184320

// ---------------- static device scratch ------------------------------------
__device__ int   g_keep[BB];
__device__ int   g_npairs;
__device__ int2  g_pairs[512];
__device__ int   g_ybase[NSLOT*PS], g_ylen[NSLOT*PS];
__device__ int   g_xbase[NSLOT*PS], g_xlen[NSLOT*PS];
__device__ float g_ft[BB*FM2*C0];
__device__ __half g_pp[(size_t)NSLOT*NPOS*C0];    // pooled fp16
__device__ __half g_x1[(size_t)NSLOT*NPOS*C1];    // stage1 out fp16
__device__ float  g_x2[(size_t)NSLOT*NPOS*C2];
__device__ __half g_W1b[2u*NCH1*256*KC];          // [term][kc][oc][64] fp16 hi/lo
__device__ __half g_W2b[2u*NCH2*256*KC];
__device__ float  g_W3t[C2*C3];

// ---------------- PTX helpers (family-agnostic ISA only) --------------------
__device__ __forceinline__ uint32_t smem_u32(const void* p) {
    uint32_t a;
    asm("{ .reg .u64 t; cvta.to.shared.u64 t, %1; cvt.u32.u64 %0, t; }" : "=r"(a) : "l"(p));
    return a;
}
__device__ __forceinline__ void cpa16(uint32_t dst, const void* src, int ok) {
    int sz = ok ? 16 : 0;
    asm volatile("cp.async.cg.shared.global [%0], [%1], 16, %2;"
                 :: "r"(dst), "l"(src), "r"(sz) : "memory");
}
__device__ __forceinline__ void cpa_commit() {
    asm volatile("cp.async.commit_group;" ::: "memory");
}
__device__ __forceinline__ void ldsm4(uint32_t* r, uint32_t a) {
    asm volatile("ldmatrix.sync.aligned.m8n8.x4.shared.b16 {%0,%1,%2,%3}, [%4];"
                 : "=r"(r[0]), "=r"(r[1]), "=r"(r[2]), "=r"(r[3]) : "r"(a));
}
__device__ __forceinline__ void mma_f16(float* c, const uint32_t* a, const uint32_t* b) {
    asm volatile("mma.sync.aligned.m16n8k16.row.col.f32.f16.f16.f32 "
                 "{%0,%1,%2,%3}, {%4,%5,%6,%7}, {%8,%9}, {%0,%1,%2,%3};"
                 : "+f"(c[0]), "+f"(c[1]), "+f"(c[2]), "+f"(c[3])
                 : "r"(a[0]), "r"(a[1]), "r"(a[2]), "r"(a[3]), "r"(b[0]), "r"(b[1]));
}

// ---------------- ROI decode + compaction (also zeros er region) ------------
__global__ void k_setup(const float* __restrict__ roi, float* __restrict__ out) {
    int b = blockIdx.x, r = threadIdx.x;
    const float* p = roi + (size_t)(b*RR + r)*5;
    int rl[4], cc[4];
#pragma unroll
    for (int k = 0; k < 4; ++k) {
        float v = p[1+k] * 18.75f;
        rl[k] = (int)v;
        int c = rl[k] < 0 ? 0 : rl[k];
        cc[k] = c > SMAXC ? SMAXC : c;
    }
    int valid = (cc[2] > cc[0]) && (cc[3] > cc[1]);

    // zero own er slot first (replaces global memset for this region)
#pragma unroll
    for (int k = 0; k < 4; ++k) out[OUT_ER + (b*RR + r)*4 + k] = 0.f;

    __shared__ int flags[RR], pre[RR];
    flags[r] = valid;
    __syncthreads();
    if (r == 0) {
        int run = 0;
        for (int i = 0; i < RR; ++i) { pre[i] = run; run += flags[i]; }
        g_keep[b] = run;
        out[OUT_KEEP + b] = (float)run;
    }
    __syncthreads();

    if (valid) {
        int slot = b*RR + pre[r];
#pragma unroll
        for (int k = 0; k < 4; ++k)
            out[OUT_ER + slot*4 + k] = (float)rl[k] * (16.0f/300.0f);
        int xmin = cc[0], ymin = cc[1], xmax = cc[2], ymax = cc[3];
        int Hy = ymax - ymin + 1, Hx = xmax - xmin + 1;
#pragma unroll
        for (int i = 0; i < PS; ++i) {
            int sy = (i*Hy)/PS,  ey = ((i+1)*Hy + PS - 1)/PS;
            g_ybase[slot*PS+i] = ymin + sy;  g_ylen[slot*PS+i] = ey - sy;
            int sx = (i*Hx)/PS,  ex = ((i+1)*Hx + PS - 1)/PS;
            g_xbase[slot*PS+i] = xmin + sx;  g_xlen[slot*PS+i] = ex - sx;
        }
    }
}

__global__ void k_pairs() {
    if (threadIdx.x == 0) {
        int n = 0;
        for (int b = 0; b < BB; ++b) {
            int np = (g_keep[b] + 1) >> 1;
            for (int j = 0; j < np; ++j) g_pairs[n++] = make_int2(b, j);
        }
        g_npairs = n;
    }
}

// ---------------- features [b][c][y][x] -> [b][yx][c] -----------------------
__global__ void k_ftrans(const float* __restrict__ f) {
    __shared__ float t[32][33];
    int b  = blockIdx.z;
    int yx0 = blockIdx.x*32, c0 = blockIdx.y*32;
    int tx = threadIdx.x, ty = threadIdx.y;
    int yx = yx0 + tx, c = c0 + ty;
    if (yx < FM2) t[ty][tx] = f[((size_t)b*C0 + c)*FM2 + yx];
    __syncthreads();
    int c2 = c0 + tx, yx2 = yx0 + ty;
    if (yx2 < FM2) g_ft[((size_t)b*FM2 + yx2)*C0 + c2] = t[tx][ty];
}

// ---------------- weight split: [oc][ic][3][3] -> [term][kc][oc][64] fp16 ---
template<int IC>
__global__ void k_wsplit(const float* __restrict__ W) {
    constexpr int ICB = IC/KC;
    constexpr int NC  = 9*ICB;
    __half* Wb = (IC == 1024) ? g_W1b : g_W2b;
    int e = blockIdx.x*256 + threadIdx.x;
    int term = e / (NC*256*KC);
    int rem  = e % (NC*256*KC);
    int kc = rem >> 14, r2 = rem & 16383, oc = r2 >> 6, t = r2 & 63;
    int tap = kc / ICB, icb = kc % ICB;
    int ic = icb*KC + t;
    float w = W[((size_t)oc*IC + ic)*9 + tap];
    __half h = __float2half_rn(w);
    float val = term ? (w - __half2float(h)) : w;
    Wb[e] = __float2half_rn(val);
}

__global__ void k_w3t(const float* __restrict__ w) {
    int oc = blockIdx.x, ic = threadIdx.x;
    g_W3t[ic*C3 + oc] = w[oc*C2 + ic];
}

// ---------------- adaptive pooling -> fp16 ----------------------------------
__global__ void k_pool() {
    int b = blockIdx.z, j = blockIdx.y;
    if (j >= g_keep[b]) return;
    int slot = b*RR + j;
    int c = blockIdx.x*128 + threadIdx.x;

    __shared__ int yb[PS], yl[PS], xb[PS], xl[PS];
    if (threadIdx.x < PS) {
        int i = threadIdx.x;
        yb[i] = g_ybase[slot*PS+i]; yl[i] = g_ylen[slot*PS+i];
        xb[i] = g_xbase[slot*PS+i]; xl[i] = g_xlen[slot*PS+i];
    }
    __syncthreads();

    const float* fb = g_ft + (size_t)b*FM2*C0 + c;
#pragma unroll
    for (int p = 0; p < PS; ++p) {
        int y0 = yb[p], ny = yl[p];
        float ry = 1.0f/(float)ny;
#pragma unroll
        for (int q = 0; q < PS; ++q) {
            int x0 = xb[q], nx = xl[q];
            float s = 0.f;
            for (int dy = 0; dy < ny; ++dy) {
                const float* row = fb + ((size_t)((y0+dy)*FM + x0))*C0;
                for (int dx = 0; dx < nx; ++dx) s += row[(size_t)dx*C0];
            }
            s = s * ry * (1.0f/(float)nx);
            g_pp[((size_t)slot*NPOS + p*PS + q)*C0 + c] = __float2half_rn(s);
        }
    }
}

// ---------------- mma.sync fp16 implicit-GEMM 3x3 conv + BN + ReLU ----------
// CTA: M=128 (2 ROIs x49+pad), N=256, 512 thr = 16 warps (2Mx8N), warp 64x32.
// Products: a*bh + a*bl (weights exact to ~22 bits, activations fp16).
template<int STAGE>
__global__ void __launch_bounds__(512, 1) k_mma(
    const float* __restrict__ bias, const float* __restrict__ gg,
    const float* __restrict__ be,   const float* __restrict__ mm,
    const float* __restrict__ vv)
{
    constexpr int IC  = (STAGE == 1) ? C0 : C1;
    constexpr int ICB = IC/KC;
    constexpr int NC  = 9*ICB;

    int bx = blockIdx.x;
    if (bx >= g_npairs) return;
    int2 pr2 = g_pairs[bx];
    int b = pr2.x, j = pr2.y;
    int keep = g_keep[b];
    int slot0 = b*RR + 2*j;
    int tid = threadIdx.x, wid = tid >> 5, lane = tid & 31;
    int wm = wid >> 3, wn = wid & 7;
    int R0 = wm*64, Cw = wn*32;

    const __half* inA = (STAGE == 1) ? g_pp  : g_x1;
    const __half* Wb  = (STAGE == 1) ? g_W1b : g_W2b;

    extern __shared__ __align__(16) char dyn[];
    uint32_t base = smem_u32(dyn);

    __shared__ float s_sc[256], s_sh[256];
    if (tid < 256) {
        float sc = gg[tid] * rsqrtf(vv[tid] + 1e-5f);
        s_sc[tid] = sc;
        s_sh[tid] = bias[tid]*sc + be[tid] - mm[tid]*sc;
    }

    auto stage = [&](int c, int buf) {
        int tap = c / ICB, icb = c - tap*ICB;
        int ky = tap/3, kx = tap - ky*3;
        // A: 128 rows x 8 units of 16B, 2 per thread
#pragma unroll
        for (int i = 0; i < 2; ++i) {
            int g = tid + i*512;
            int row = g >> 3, u = g & 7;
            int r2 = row >= 49 ? 1 : 0;
            int p = row - 49*r2;
            int py = p/7, px = p - py*7;
            int sy = py + ky - 1, sx = px + kx - 1;
            int ok = (row < 98) && ((2*j + r2) < keep) &&
                     sy >= 0 && sy < 7 && sx >= 0 && sx < 7;
            size_t off = ok ? (((size_t)(slot0 + r2)*NPOS + sy*7 + sx)*IC + icb*KC + u*8) : 0;
            cpa16(base + buf*BUF + row*STRD + u*16, inA + off, ok);
        }
        // B: 2 terms x 256 rows x 8 units, 8 per thread
#pragma unroll
        for (int t2 = 0; t2 < 2; ++t2) {
            const __half* ws = Wb + ((size_t)t2*NC + c)*256*KC;
            uint32_t dB = base + buf*BUF + A_T + t2*B_T;
#pragma unroll
            for (int i = 0; i < 4; ++i) {
                int g = tid + i*512;
                int r = g >> 3, u = g & 7;
                cpa16(dB + r*STRD + u*16, ws + (size_t)r*KC + u*8, 1);
            }
        }
    };

    float acc[64];
#pragma unroll
    for (int i = 0; i < 64; ++i) acc[i] = 0.f;

    stage(0, 0); cpa_commit();
    stage(1, 1); cpa_commit();

    int arow = lane & 15, asel = lane >> 4;
    int brow = (lane & 7) + ((lane >> 4) << 3), bsel = (lane >> 3) & 1;

#pragma unroll 1
    for (int c = 0; c < NC; ++c) {
        if (c + 1 < NC) asm volatile("cp.async.wait_group 1;" ::: "memory");
        else            asm volatile("cp.async.wait_group 0;" ::: "memory");
        __syncthreads();

        int buf = c & 1;
        uint32_t Asm = base + buf*BUF;
        uint32_t Bh  = Asm + A_T;
        uint32_t Bl  = Bh + B_T;

#pragma unroll
        for (int ks = 0; ks < 4; ++ks) {
            uint32_t au = (2*ks + asel)*16;
            uint32_t bu = (2*ks + bsel)*16;
            uint32_t a[16], bfr[8];
#pragma unroll
            for (int i = 0; i < 4; ++i)
                ldsm4(a + 4*i, Asm + (R0 + i*16 + arow)*STRD + au);
#pragma unroll
            for (int h = 0; h < 2; ++h)
                ldsm4(bfr + 4*h, Bh + (Cw + h*16 + brow)*STRD + bu);
#pragma unroll
            for (int i = 0; i < 4; ++i)
#pragma unroll
                for (int jj = 0; jj < 4; ++jj)
                    mma_f16(acc + (i*4+jj)*4, a + 4*i, bfr + (jj>>1)*4 + (jj&1)*2);
#pragma unroll
            for (int h = 0; h < 2; ++h)
                ldsm4(bfr + 4*h, Bl + (Cw + h*16 + brow)*STRD + bu);
#pragma unroll
            for (int i = 0; i < 4; ++i)
#pragma unroll
                for (int jj = 0; jj < 4; ++jj)
                    mma_f16(acc + (i*4+jj)*4, a + 4*i, bfr + (jj>>1)*4 + (jj&1)*2);
        }
        __syncthreads();
        if (c + 2 < NC) { stage(c + 2, buf); cpa_commit(); }
    }

    // ---- epilogue: BN + ReLU, scatter to [slot][pos][oc] ----
#pragma unroll
    for (int i = 0; i < 4; ++i) {
#pragma unroll
        for (int half = 0; half < 2; ++half) {
            int m = R0 + i*16 + (lane >> 2) + half*8;
            int r2 = m >= 49 ? 1 : 0;
            int p = m - 49*r2;
            if (m < 98 && (2*j + r2) < keep) {
                size_t ob = ((size_t)(slot0 + r2)*NPOS + p)*256;
#pragma unroll
                for (int jj = 0; jj < 4; ++jj) {
                    int col = Cw + jj*8 + (lane & 3)*2;
                    float v0 = fmaf(acc[(i*4+jj)*4 + half*2    ], s_sc[col],   s_sh[col]);
                    float v1 = fmaf(acc[(i*4+jj)*4 + half*2 + 1], s_sc[col+1], s_sh[col+1]);
                    v0 = v0 > 0.f ? v0 : 0.f;
                    v1 = v1 > 0.f ? v1 : 0.f;
                    if (STAGE == 1) {
                        unsigned hp = ((unsigned)__half_as_ushort(__float2half_rn(v1)) << 16)
                                    | __half_as_ushort(__float2half_rn(v0));
                        ((unsigned*)g_x1)[(ob + col) >> 1] = hp;
                    } else {
                        *(float2*)(g_x2 + ob + col) = make_float2(v0, v1);
                    }
                }
            }
        }
    }
}

// ---------------- 1x1 conv + BN + ReLU -> final output (zeros tail) ---------
__global__ void k_conv1x1(const float* __restrict__ gg, const float* __restrict__ be,
                          const float* __restrict__ mm, const float* __restrict__ vv,
                          float* __restrict__ out)
{
    int b = blockIdx.x >> 7, j = blockIdx.x & 127;
    int slot = blockIdx.x;
    if (j >= g_keep[b]) {
        // invalid slot: zero its 32x49 output block (d_out is poisoned)
        for (int idx = threadIdx.x; idx < C3*NPOS; idx += 256)
            out[OUT_FEAT + (size_t)slot*C3*NPOS + idx] = 0.f;
        return;
    }

    __shared__ float sw[C2*C3];
    for (int i = threadIdx.x; i < C2*C3; i += 256) sw[i] = g_W3t[i];
    __syncthreads();

    const float* xp = g_x2 + (size_t)slot*NPOS*C2;
    for (int idx = threadIdx.x; idx < NPOS*C3; idx += 256) {
        int oc = idx & 31, pos = idx >> 5;
        const float* xr = xp + (size_t)pos*C2;
        float acc = 0.f;
#pragma unroll 8
        for (int ic = 0; ic < C2; ++ic) acc = fmaf(xr[ic], sw[ic*C3 + oc], acc);
        float sc = gg[oc] * rsqrtf(vv[oc] + 1e-5f);
        float sh = be[oc] - mm[oc]*sc;
        float val = fmaf(acc, sc, sh);
        out[OUT_FEAT + ((size_t)slot*C3 + oc)*NPOS + pos] = val > 0.f ? val : 0.f;
    }
}

// ---------------------------------------------------------------------------
extern "C" void kernel_launch(void* const* d_in, const int* in_sizes, int n_in,
                              void* d_out, int out_size) {
    const float* roi  = (const float*)d_in[0];
    const float* feat = (const float*)d_in[1];
    const float* W1   = (const float*)d_in[2];
    const float* b1   = (const float*)d_in[3];
    const float* g1   = (const float*)d_in[4];
    const float* be1  = (const float*)d_in[5];
    const float* m1   = (const float*)d_in[6];
    const float* v1   = (const float*)d_in[7];
    const float* W2   = (const float*)d_in[8];
    const float* b2   = (const float*)d_in[9];
    const float* g2   = (const float*)d_in[10];
    const float* be2  = (const float*)d_in[11];
    const float* m2   = (const float*)d_in[12];
    const float* v2   = (const float*)d_in[13];
    const float* W3   = (const float*)d_in[14];
    const float* g3   = (const float*)d_in[15];
    const float* be3  = (const float*)d_in[16];
    const float* m3   = (const float*)d_in[17];
    const float* v3   = (const float*)d_in[18];
    float* out = (float*)d_out;

    cudaFuncSetAttribute(k_mma<1>, cudaFuncAttributeMaxDynamicSharedMemorySize, DSMEM);
    cudaFuncSetAttribute(k_mma<2>, cudaFuncAttributeMaxDynamicSharedMemorySize, DSMEM);

    // launch order chosen so k_mma<1> is launch #5 (0-based) -> ncu -s 5 captures it
    k_setup<<<BB, RR>>>(roi, out);                           // 0
    k_pairs<<<1, 32>>>();                                    // 1
    k_ftrans<<<dim3(12, 32, BB), dim3(32, 32)>>>(feat);      // 2
    k_wsplit<C0><<<2*NCH1*256*KC/256, 256>>>(W1);            // 3
    k_pool<<<dim3(8, RR, BB), 128>>>();                      // 4
    k_mma<1><<<512, 512, DSMEM>>>(b1, g1, be1, m1, v1);      // 5  <- profiled
    k_wsplit<C1><<<2*NCH2*256*KC/256, 256>>>(W2);            // 6
    k_w3t<<<C3, C2>>>(W3);                                   // 7
    k_mma<2><<<512, 512, DSMEM>>>(b2, g2, be2, m2, v2);      // 8
    k_conv1x1<<<NSLOT, 256>>>(g3, be3, m3, v3, out);         // 9
}